// round 7
// baseline (speedup 1.0000x reference)
#include <cuda_runtime.h>

typedef unsigned long long u64;
typedef unsigned int u32;

#define NQ 22
#define DIM (1u << 22)

__device__ float2 g_buf0[DIM];
__device__ float2 g_buf1[DIM];
// per (layer,qubit): {u00r,u00i,-u00i, u01r,u01i,-u01i, u10r,u10i,-u10i, u11r,u11i,-u11i}
__device__ u64 g_gpk[4 * 22 * 12];
__device__ float g_norm;
__device__ float g_acc[NQ];

// ---------- packed f32x2 helpers ----------
__device__ __forceinline__ u64 pmul(u64 a, u64 b) {
    u64 d; asm("mul.rn.f32x2 %0, %1, %2;" : "=l"(d) : "l"(a), "l"(b)); return d;
}
__device__ __forceinline__ u64 pfma(u64 a, u64 b, u64 c) {
    u64 d; asm("fma.rn.f32x2 %0, %1, %2, %3;" : "=l"(d) : "l"(a), "l"(b), "l"(c)); return d;
}
__device__ __forceinline__ u64 pk2(float lo, float hi) {
    return ((u64)__float_as_uint(hi) << 32) | (u64)__float_as_uint(lo);
}
__device__ __forceinline__ float plo(u64 v) { return __uint_as_float((u32)v); }
__device__ __forceinline__ float phi(u64 v) { return __uint_as_float((u32)(v >> 32)); }

// XOR-linear swizzle on 8B slot index; full-rank on every round's lane-varying bits
__host__ __device__ constexpr u32 swz(u32 j) { return j ^ ((j >> 3) & 15u) ^ ((j >> 7) & 15u); }

// ---------- gate precompute ----------
__global__ void k_gates(const float* __restrict__ P) {
    int t = threadIdx.x;
    if (t < NQ) g_acc[t] = 0.f;
    if (t == NQ) g_norm = 0.f;
    if (t >= 88) return;  // t = l*22 + q
    float tx = P[t * 3 + 0], ty = P[t * 3 + 1], tz = P[t * 3 + 2];
    float cx = cosf(0.5f * tx), sx = sinf(0.5f * tx);
    float cy = cosf(0.5f * ty), sy = sinf(0.5f * ty);
    float cz = cosf(0.5f * tz), sz = sinf(0.5f * tz);
    float m00r = cy * cx, m00i = sy * sx;
    float m01r = -sy * cx, m01i = -cy * sx;
    float m10r = sy * cx, m10i = -cy * sx;
    float m11r = cy * cx, m11i = -sy * sx;
    float u00r = cz * m00r + sz * m00i, u00i = cz * m00i - sz * m00r;
    float u01r = cz * m01r + sz * m01i, u01i = cz * m01i - sz * m01r;
    float u10r = cz * m10r - sz * m10i, u10i = cz * m10i + sz * m10r;
    float u11r = cz * m11r - sz * m11i, u11i = cz * m11i + sz * m11r;
    float vals[12] = { u00r, u00i, -u00i, u01r, u01i, -u01i,
                       u10r, u10i, -u10i, u11r, u11i, -u11i };
    u64* W = g_gpk + t * 12;
#pragma unroll
    for (int i = 0; i < 12; i++) {
        u32 b = __float_as_uint(vals[i]);
        W[i] = ((u64)b << 32) | (u64)b;
    }
}

__global__ void k_final(float* __restrict__ out) {
    if (threadIdx.x < NQ) out[threadIdx.x] = g_acc[threadIdx.x] / g_norm;
}

// ---------- register gate on bit G of an 8-slot window ----------
template <int G>
__device__ __forceinline__ void gate8(u64* RE, u64* IM, const u64* W) {
    u64 p00r = W[0], p00i = W[1], n00i = W[2], p01r = W[3], p01i = W[4], n01i = W[5];
    u64 p10r = W[6], p10i = W[7], n10i = W[8], p11r = W[9], p11i = W[10], n11i = W[11];
#pragma unroll
    for (int h = 0; h < 4; h++) {
        const int m0 = ((h >> G) << (G + 1)) | (h & ((1 << G) - 1));
        const int m1 = m0 | (1 << G);
        u64 ar = RE[m0], ai = IM[m0], br = RE[m1], bi = IM[m1];
        u64 t0 = pmul(p00r, ar); t0 = pfma(n00i, ai, t0); t0 = pfma(p01r, br, t0); t0 = pfma(n01i, bi, t0);
        u64 t1 = pmul(p00i, ar); t1 = pfma(p00r, ai, t1); t1 = pfma(p01i, br, t1); t1 = pfma(p01r, bi, t1);
        u64 t2 = pmul(p10r, ar); t2 = pfma(n10i, ai, t2); t2 = pfma(p11r, br, t2); t2 = pfma(n11i, bi, t2);
        u64 t3 = pmul(p10i, ar); t3 = pfma(p10r, ai, t3); t3 = pfma(p11i, br, t3); t3 = pfma(p11r, bi, t3);
        RE[m0] = t0; IM[m0] = t1; RE[m1] = t2; IM[m1] = t3;
    }
}
template <int G>
__device__ __forceinline__ void gate4(u64* RE, u64* IM, const u64* W) {
    u64 p00r = W[0], p00i = W[1], n00i = W[2], p01r = W[3], p01i = W[4], n01i = W[5];
    u64 p10r = W[6], p10i = W[7], n10i = W[8], p11r = W[9], p11i = W[10], n11i = W[11];
#pragma unroll
    for (int h = 0; h < 2; h++) {
        const int m0 = ((h >> G) << (G + 1)) | (h & ((1 << G) - 1));
        const int m1 = m0 | (1 << G);
        u64 ar = RE[m0], ai = IM[m0], br = RE[m1], bi = IM[m1];
        u64 t0 = pmul(p00r, ar); t0 = pfma(n00i, ai, t0); t0 = pfma(p01r, br, t0); t0 = pfma(n01i, bi, t0);
        u64 t1 = pmul(p00i, ar); t1 = pfma(p00r, ai, t1); t1 = pfma(p01i, br, t1); t1 = pfma(p01r, bi, t1);
        u64 t2 = pmul(p10r, ar); t2 = pfma(n10i, ai, t2); t2 = pfma(p11r, br, t2); t2 = pfma(n11i, bi, t2);
        u64 t3 = pmul(p10i, ar); t3 = pfma(p10r, ai, t3); t3 = pfma(p11i, br, t3); t3 = pfma(p11r, bi, t3);
        RE[m0] = t0; IM[m0] = t1; RE[m1] = t2; IM[m1] = t3;
    }
}

// ---------- smem window load/store, XOR-linear addressing (tb8 = swz(tbase)*8) ----------
template <int S, int IMOFF>
__device__ __forceinline__ void lds8(u64* RE, u64* IM, const char* s, u32 tb8) {
#pragma unroll
    for (int m = 0; m < 8; m++) {
        u32 a = tb8 ^ (swz((u32)m << S) * 8u);
        RE[m] = *(const u64*)(s + a);
        IM[m] = *(const u64*)(s + a + IMOFF);
    }
}
template <int S, int IMOFF>
__device__ __forceinline__ void sts8(const u64* RE, const u64* IM, char* s, u32 tb8) {
#pragma unroll
    for (int m = 0; m < 8; m++) {
        u32 a = tb8 ^ (swz((u32)m << S) * 8u);
        *(u64*)(s + a) = RE[m];
        *(u64*)(s + a + IMOFF) = IM[m];
    }
}
template <int S, int IMOFF>
__device__ __forceinline__ void lds4(u64* RE, u64* IM, const char* s, u32 tb8) {
#pragma unroll
    for (int m = 0; m < 4; m++) {
        u32 a = tb8 ^ (swz((u32)m << S) * 8u);
        RE[m] = *(const u64*)(s + a);
        IM[m] = *(const u64*)(s + a + IMOFF);
    }
}

// ============ Pass A: gates glob bits 0..10 (wires 21..11). Tile 4096 amps (glob 0..11),
// pack on glob bit 11. Rounds: R0 bits 3-5 (gmem load), R1 bits 0-2, R2 bits 6-8,
// R3 bits 9-10 (gmem store). Slot space 11 bits, 2048 slots. ============
__device__ __forceinline__ void passA_tail(char* s, const u64* sg, u32 T, u32 base) {
    const int IMOFF = 16384;
    u64 RE[8], IM[8];
    // R1: S=0, slot bits 0,1,2 -> wires 21,20,19
    u32 tb = swz(T << 3) * 8u;
    lds8<0, IMOFF>(RE, IM, s, tb);
    gate8<0>(RE, IM, sg + 21 * 12);
    gate8<1>(RE, IM, sg + 20 * 12);
    gate8<2>(RE, IM, sg + 19 * 12);
    sts8<0, IMOFF>(RE, IM, s, tb);
    __syncthreads();
    // R2: S=6, bits 6,7,8 -> wires 15,14,13
    tb = swz(((T >> 6) << 9) | (T & 63u)) * 8u;
    lds8<6, IMOFF>(RE, IM, s, tb);
    gate8<0>(RE, IM, sg + 15 * 12);
    gate8<1>(RE, IM, sg + 14 * 12);
    gate8<2>(RE, IM, sg + 13 * 12);
    sts8<6, IMOFF>(RE, IM, s, tb);
    __syncthreads();
    // R3: bits 9,10 -> wires 12,11 (4-slot windows, 2 subs), fused store
#pragma unroll
    for (int v = 0; v < 2; v++) {
        u32 V = ((u32)v << 8) | T;
        u32 tb4 = swz(V) * 8u;
        lds4<9, IMOFF>(RE, IM, s, tb4);
        gate4<0>(RE, IM, sg + 12 * 12);
        gate4<1>(RE, IM, sg + 11 * 12);
#pragma unroll
        for (int m = 0; m < 4; m++) {
            u32 amp = base | ((u32)m << 9) | V;
            float2 lo; lo.x = plo(RE[m]); lo.y = plo(IM[m]);
            float2 hi; hi.x = phi(RE[m]); hi.y = phi(IM[m]);
            g_buf0[amp] = lo;
            g_buf0[amp | 0x800u] = hi;
        }
    }
}

__global__ void __launch_bounds__(256, 3) k_passA0(const float* __restrict__ re_in,
                                                   const float* __restrict__ im_in) {
    __shared__ char s[32768];
    __shared__ u64 s_gate[264];
    __shared__ float s_nrm[8];
    const int IMOFF = 16384;
    u32 T = threadIdx.x;
    u32 base = (u32)blockIdx.x << 12;
    for (u32 i = T; i < 264; i += 256) s_gate[i] = g_gpk[i];  // layer 0

    u64 RE[8], IM[8];
    u64 nacc = 0;
    u32 tbase = ((T >> 3) << 6) | (T & 7u);
#pragma unroll
    for (int m = 0; m < 8; m++) {
        u32 j = tbase | ((u32)m << 3);
        u32 a0 = base | j, a1 = a0 | 0x800u;
        RE[m] = pk2(re_in[a0], re_in[a1]);
        IM[m] = pk2(im_in[a0], im_in[a1]);
        nacc = pfma(RE[m], RE[m], nacc);
        nacc = pfma(IM[m], IM[m], nacc);
    }
    float nrm = plo(nacc) + phi(nacc);
#pragma unroll
    for (int o = 16; o > 0; o >>= 1) nrm += __shfl_down_sync(0xffffffffu, nrm, o);
    if ((T & 31) == 0) s_nrm[T >> 5] = nrm;
    __syncthreads();  // staging + s_nrm visible
    if (T == 0) {
        float sum = 0.f;
#pragma unroll
        for (int w = 0; w < 8; w++) sum += s_nrm[w];
        atomicAdd(&g_norm, sum);
    }
    // R0: window bits 3,4,5 -> wires 18,17,16
    gate8<0>(RE, IM, s_gate + 18 * 12);
    gate8<1>(RE, IM, s_gate + 17 * 12);
    gate8<2>(RE, IM, s_gate + 16 * 12);
    sts8<3, IMOFF>(RE, IM, s, swz(tbase) * 8u);
    __syncthreads();
    passA_tail(s, s_gate, T, base);
}

__global__ void __launch_bounds__(256, 3) k_passAg(int layer) {
    __shared__ char s[32768];
    __shared__ u64 s_gate[264];
    const int IMOFF = 16384;
    u32 T = threadIdx.x;
    u32 base = (u32)blockIdx.x << 12;
    for (u32 i = T; i < 264; i += 256) s_gate[i] = g_gpk[layer * 264 + i];

    u64 RE[8], IM[8];
    u32 tbase = ((T >> 3) << 6) | (T & 7u);
#pragma unroll
    for (int m = 0; m < 8; m++) {
        u32 g0 = base | tbase | ((u32)m << 3);
        u32 a0 = g0 ^ (g0 >> 1);   // binary->Gray: fused inverse CNOT chain
        u32 a1 = a0 ^ 0xC00u;      // pack partner (glob bit 11 flipped pre-perm)
        float2 v0 = g_buf1[a0], v1 = g_buf1[a1];
        RE[m] = pk2(v0.x, v1.x);
        IM[m] = pk2(v0.y, v1.y);
    }
    __syncthreads();  // staging visible
    gate8<0>(RE, IM, s_gate + 18 * 12);
    gate8<1>(RE, IM, s_gate + 17 * 12);
    gate8<2>(RE, IM, s_gate + 16 * 12);
    sts8<3, IMOFF>(RE, IM, s, swz(tbase) * 8u);
    __syncthreads();
    passA_tail(s, s_gate, T, base);
}

// ============ Pass B: gates glob bits 11..21 (wires 10..0). Tile = glob {11..21}+{0,1},
// pack on glob bit 0. Slot e (12 bits): e0 = glob1, e[1..11] = glob[11..21].
// Rounds: R0 e-bits 1,2 (gmem float4 load), R1 e3-5, R2 e6-8, R3 e9-11 (store/reduce). ============
__device__ __forceinline__ u32 gbOf(u32 e, u32 bb) {
    return ((e >> 1) << 11) | (bb << 2) | ((e & 1u) << 1);
}

__device__ __forceinline__ void passB_R0to2(const u64* sg, char* s, u32 T, u32 bb) {
    const int IMOFF = 32768;
    // R0: e = Tp<<3 | m'  (m' bits: e0=v ungated, e1,e2 gated -> wires 10,9)
#pragma unroll
    for (int vp = 0; vp < 2; vp++) {
        u32 Tp = ((u32)vp << 8) | T;
        u64 RE[8], IM[8];
#pragma unroll
        for (int mp = 0; mp < 8; mp++) {
            u32 e = (Tp << 3) | (u32)mp;
            float4 v = *(const float4*)&g_buf0[gbOf(e, bb) & ~1u];
            RE[mp] = pk2(v.x, v.z);
            IM[mp] = pk2(v.y, v.w);
        }
        gate8<1>(RE, IM, sg + 10 * 12);
        gate8<2>(RE, IM, sg + 9 * 12);
        sts8<0, IMOFF>(RE, IM, s, swz(Tp << 3) * 8u);
    }
    __syncthreads();
    // R1: S=3, e-bits 3,4,5 -> wires 8,7,6
#pragma unroll
    for (int vp = 0; vp < 2; vp++) {
        u32 Tp = ((u32)vp << 8) | T;
        u64 RE[8], IM[8];
        u32 tb = swz(((Tp >> 3) << 6) | (Tp & 7u)) * 8u;
        lds8<3, IMOFF>(RE, IM, s, tb);
        gate8<0>(RE, IM, sg + 8 * 12);
        gate8<1>(RE, IM, sg + 7 * 12);
        gate8<2>(RE, IM, sg + 6 * 12);
        sts8<3, IMOFF>(RE, IM, s, tb);
    }
    __syncthreads();
    // R2: S=6, e-bits 6,7,8 -> wires 5,4,3
#pragma unroll
    for (int vp = 0; vp < 2; vp++) {
        u32 Tp = ((u32)vp << 8) | T;
        u64 RE[8], IM[8];
        u32 tb = swz(((Tp >> 6) << 9) | (Tp & 63u)) * 8u;
        lds8<6, IMOFF>(RE, IM, s, tb);
        gate8<0>(RE, IM, sg + 5 * 12);
        gate8<1>(RE, IM, sg + 4 * 12);
        gate8<2>(RE, IM, sg + 3 * 12);
        sts8<6, IMOFF>(RE, IM, s, tb);
    }
    __syncthreads();
}

__global__ void __launch_bounds__(256, 3) k_passB(int layer) {
    extern __shared__ char s[];   // 64KB
    __shared__ u64 s_gate[264];
    const int IMOFF = 32768;
    u32 T = threadIdx.x, bb = blockIdx.x;
    for (u32 i = T; i < 264; i += 256) s_gate[i] = g_gpk[layer * 264 + i];
    __syncthreads();
    passB_R0to2(s_gate, s, T, bb);
    // R3: e-bits 9,10,11 -> wires 2,1,0; fused float4 store
#pragma unroll
    for (int vp = 0; vp < 2; vp++) {
        u32 Tp = ((u32)vp << 8) | T;
        u64 RE[8], IM[8];
        u32 tb = swz(Tp) * 8u;
        lds8<9, IMOFF>(RE, IM, s, tb);
        gate8<0>(RE, IM, s_gate + 2 * 12);
        gate8<1>(RE, IM, s_gate + 1 * 12);
        gate8<2>(RE, IM, s_gate + 0 * 12);
#pragma unroll
        for (int m = 0; m < 8; m++) {
            u32 e = ((u32)m << 9) | Tp;
            float4 v; v.x = plo(RE[m]); v.y = plo(IM[m]); v.z = phi(RE[m]); v.w = phi(IM[m]);
            *(float4*)&g_buf1[gbOf(e, bb) & ~1u] = v;
        }
    }
}

// Final pass B: fold the last CNOT permutation into indices and reduce <Z_q> directly.
__global__ void __launch_bounds__(256, 2) k_passB_last() {
    extern __shared__ char s[];
    __shared__ u64 s_gate[264];
    __shared__ float s_part[NQ * 8];
    const int IMOFF = 32768;
    u32 T = threadIdx.x, bb = blockIdx.x;
    for (u32 i = T; i < 264; i += 256) s_gate[i] = g_gpk[3 * 264 + i];
    __syncthreads();
    passB_R0to2(s_gate, s, T, bb);

    float acc[NQ];
#pragma unroll
    for (int q = 0; q < NQ; q++) acc[q] = 0.f;
#pragma unroll
    for (int vp = 0; vp < 2; vp++) {
        u32 Tp = ((u32)vp << 8) | T;
        u64 RE[8], IM[8];
        u32 tb = swz(Tp) * 8u;
        lds8<9, IMOFF>(RE, IM, s, tb);
        gate8<0>(RE, IM, s_gate + 2 * 12);
        gate8<1>(RE, IM, s_gate + 1 * 12);
        gate8<2>(RE, IM, s_gate + 0 * 12);
#pragma unroll
        for (int m = 0; m < 8; m++) {
            u32 e = ((u32)m << 9) | Tp;
            u32 glob = gbOf(e, bb);  // k=0 amp (glob bit0 = 0)
            u64 P = pfma(RE[m], RE[m], pmul(IM[m], IM[m]));
            float p0 = plo(P), p1 = phi(P);
            float sv = p0 + p1, dv = p0 - p1;
            u32 x = glob;  // forward CNOT-chain permutation (suffix xor)
            x ^= x >> 1; x ^= x >> 2; x ^= x >> 4; x ^= x >> 8; x ^= x >> 16;
#pragma unroll
            for (int q = 0; q < 21; q++)
                acc[q] += ((x >> (21 - q)) & 1u) ? -sv : sv;
            acc[21] += (x & 1u) ? -dv : dv;  // partner amp flips x bit 0 only (wire 21)
        }
    }
#pragma unroll
    for (int q = 0; q < NQ; q++) {
        float v = acc[q];
#pragma unroll
        for (int o = 16; o > 0; o >>= 1) v += __shfl_down_sync(0xffffffffu, v, o);
        if ((T & 31) == 0) s_part[q * 8 + (T >> 5)] = v;
    }
    __syncthreads();
    if (T < NQ) {
        float sum = 0.f;
#pragma unroll
        for (int w = 0; w < 8; w++) sum += s_part[T * 8 + w];
        atomicAdd(&g_acc[T], sum);
    }
}

extern "C" void kernel_launch(void* const* d_in, const int* in_sizes, int n_in,
                              void* d_out, int out_size) {
    const float* params = (const float*)d_in[0];
    const float* sre = (const float*)d_in[1];
    const float* sim = (const float*)d_in[2];
    float* out = (float*)d_out;

    cudaFuncSetAttribute(k_passB, cudaFuncAttributeMaxDynamicSharedMemorySize, 65536);
    cudaFuncSetAttribute(k_passB_last, cudaFuncAttributeMaxDynamicSharedMemorySize, 65536);

    k_gates<<<1, 128>>>(params);
    k_passA0<<<1024, 256>>>(sre, sim);
    k_passB<<<512, 256, 65536>>>(0);
    for (int l = 1; l < 4; l++) {
        k_passAg<<<1024, 256>>>(l);
        if (l < 3) k_passB<<<512, 256, 65536>>>(l);
        else       k_passB_last<<<512, 256, 65536>>>();
    }
    k_final<<<1, 32>>>(out);
}

// round 11
// speedup vs baseline: 1.1020x; 1.1020x over previous
#include <cuda_runtime.h>

typedef unsigned long long u64;
typedef unsigned int u32;

#define NQ 22
#define DIM (1u << 22)

__device__ float2 g_buf0[DIM];
__device__ float2 g_buf1[DIM];
// per (layer,qubit): {u00r,u00i,-u00i, u01r,u01i,-u01i, u10r,u10i,-u10i, u11r,u11i,-u11i}
__device__ u64 g_gpk[4 * 22 * 12];
__device__ float g_norm;
__device__ float g_acc[NQ];

// ---------- packed f32x2 helpers ----------
__device__ __forceinline__ u64 pmul(u64 a, u64 b) {
    u64 d; asm("mul.rn.f32x2 %0, %1, %2;" : "=l"(d) : "l"(a), "l"(b)); return d;
}
__device__ __forceinline__ u64 pfma(u64 a, u64 b, u64 c) {
    u64 d; asm("fma.rn.f32x2 %0, %1, %2, %3;" : "=l"(d) : "l"(a), "l"(b), "l"(c)); return d;
}
__device__ __forceinline__ u64 pk2(float lo, float hi) {
    return ((u64)__float_as_uint(hi) << 32) | (u64)__float_as_uint(lo);
}
__device__ __forceinline__ float plo(u64 v) { return __uint_as_float((u32)v); }
__device__ __forceinline__ float phi(u64 v) { return __uint_as_float((u32)(v >> 32)); }

// XOR-linear swizzle on 8B slot index; verified conflict-free for all round windows below
__host__ __device__ constexpr u32 swz(u32 j) { return j ^ ((j >> 3) & 15u) ^ ((j >> 7) & 15u); }

// ---------- gate precompute ----------
__global__ void k_gates(const float* __restrict__ P) {
    int t = threadIdx.x;
    if (t < NQ) g_acc[t] = 0.f;
    if (t == NQ) g_norm = 0.f;
    if (t >= 88) return;  // t = l*22 + q
    float tx = P[t * 3 + 0], ty = P[t * 3 + 1], tz = P[t * 3 + 2];
    float cx = cosf(0.5f * tx), sx = sinf(0.5f * tx);
    float cy = cosf(0.5f * ty), sy = sinf(0.5f * ty);
    float cz = cosf(0.5f * tz), sz = sinf(0.5f * tz);
    float m00r = cy * cx, m00i = sy * sx;
    float m01r = -sy * cx, m01i = -cy * sx;
    float m10r = sy * cx, m10i = -cy * sx;
    float m11r = cy * cx, m11i = -sy * sx;
    float u00r = cz * m00r + sz * m00i, u00i = cz * m00i - sz * m00r;
    float u01r = cz * m01r + sz * m01i, u01i = cz * m01i - sz * m01r;
    float u10r = cz * m10r - sz * m10i, u10i = cz * m10i + sz * m10r;
    float u11r = cz * m11r - sz * m11i, u11i = cz * m11i + sz * m11r;
    float vals[12] = { u00r, u00i, -u00i, u01r, u01i, -u01i,
                       u10r, u10i, -u10i, u11r, u11i, -u11i };
    u64* W = g_gpk + t * 12;
#pragma unroll
    for (int i = 0; i < 12; i++) {
        u32 b = __float_as_uint(vals[i]);
        W[i] = ((u64)b << 32) | (u64)b;
    }
}

__global__ void k_final(float* __restrict__ out) {
    if (threadIdx.x < NQ) out[threadIdx.x] = g_acc[threadIdx.x] / g_norm;
}

// ---------- register gate on bit G of an 8-slot window ----------
template <int G>
__device__ __forceinline__ void gate8(u64* RE, u64* IM, const u64* W) {
    u64 p00r = W[0], p00i = W[1], n00i = W[2], p01r = W[3], p01i = W[4], n01i = W[5];
    u64 p10r = W[6], p10i = W[7], n10i = W[8], p11r = W[9], p11i = W[10], n11i = W[11];
#pragma unroll
    for (int h = 0; h < 4; h++) {
        const int m0 = ((h >> G) << (G + 1)) | (h & ((1 << G) - 1));
        const int m1 = m0 | (1 << G);
        u64 ar = RE[m0], ai = IM[m0], br = RE[m1], bi = IM[m1];
        u64 t0 = pmul(p00r, ar); t0 = pfma(n00i, ai, t0); t0 = pfma(p01r, br, t0); t0 = pfma(n01i, bi, t0);
        u64 t1 = pmul(p00i, ar); t1 = pfma(p00r, ai, t1); t1 = pfma(p01i, br, t1); t1 = pfma(p01r, bi, t1);
        u64 t2 = pmul(p10r, ar); t2 = pfma(n10i, ai, t2); t2 = pfma(p11r, br, t2); t2 = pfma(n11i, bi, t2);
        u64 t3 = pmul(p10i, ar); t3 = pfma(p10r, ai, t3); t3 = pfma(p11i, br, t3); t3 = pfma(p11r, bi, t3);
        RE[m0] = t0; IM[m0] = t1; RE[m1] = t2; IM[m1] = t3;
    }
}
template <int G>
__device__ __forceinline__ void gate4(u64* RE, u64* IM, const u64* W) {
    u64 p00r = W[0], p00i = W[1], n00i = W[2], p01r = W[3], p01i = W[4], n01i = W[5];
    u64 p10r = W[6], p10i = W[7], n10i = W[8], p11r = W[9], p11i = W[10], n11i = W[11];
#pragma unroll
    for (int h = 0; h < 2; h++) {
        const int m0 = ((h >> G) << (G + 1)) | (h & ((1 << G) - 1));
        const int m1 = m0 | (1 << G);
        u64 ar = RE[m0], ai = IM[m0], br = RE[m1], bi = IM[m1];
        u64 t0 = pmul(p00r, ar); t0 = pfma(n00i, ai, t0); t0 = pfma(p01r, br, t0); t0 = pfma(n01i, bi, t0);
        u64 t1 = pmul(p00i, ar); t1 = pfma(p00r, ai, t1); t1 = pfma(p01i, br, t1); t1 = pfma(p01r, bi, t1);
        u64 t2 = pmul(p10r, ar); t2 = pfma(n10i, ai, t2); t2 = pfma(p11r, br, t2); t2 = pfma(n11i, bi, t2);
        u64 t3 = pmul(p10i, ar); t3 = pfma(p10r, ai, t3); t3 = pfma(p11i, br, t3); t3 = pfma(p11r, bi, t3);
        RE[m0] = t0; IM[m0] = t1; RE[m1] = t2; IM[m1] = t3;
    }
}

// ---------- smem window ops: slot j at byte swz(j)*8; IM at +IMOFF ----------
template <int S, int IMOFF>
__device__ __forceinline__ void lds8(u64* RE, u64* IM, const char* s, u32 tb8) {
#pragma unroll
    for (int m = 0; m < 8; m++) {
        u32 a = tb8 ^ (swz((u32)m << S) * 8u);
        RE[m] = *(const u64*)(s + a);
        IM[m] = *(const u64*)(s + a + IMOFF);
    }
}
template <int S, int IMOFF>
__device__ __forceinline__ void sts8(const u64* RE, const u64* IM, char* s, u32 tb8) {
#pragma unroll
    for (int m = 0; m < 8; m++) {
        u32 a = tb8 ^ (swz((u32)m << S) * 8u);
        *(u64*)(s + a) = RE[m];
        *(u64*)(s + a + IMOFF) = IM[m];
    }
}
template <int S, int IMOFF>
__device__ __forceinline__ void lds4(u64* RE, u64* IM, const char* s, u32 tb8) {
#pragma unroll
    for (int m = 0; m < 4; m++) {
        u32 a = tb8 ^ (swz((u32)m << S) * 8u);
        RE[m] = *(const u64*)(s + a);
        IM[m] = *(const u64*)(s + a + IMOFF);
    }
}

// ============ Pass A: gates glob 0..11 (wires 21..10). Tile = glob 0..12 (8192 amps,
// 64KB), pack on glob bit 12. Slot j (12 bits) = glob 0..11. 256 thr x 16 slots (vp x8).
// R0: gmem load + window j[9..11] (wires 12,11,10)  [lanes in j0..4 -> 256B coalesced]
// R1: S=0 (wires 21,20,19)   R2: S=3 (18,17,16)  [R1->R2 warp-local]
// R3: S=6 (15,14,13) + gmem store [256B coalesced] ============
__device__ __forceinline__ void passA_R1to3(char* s, const u64* sg, u32 T, u32 base) {
    const int IMOFF = 32768;
    u64 RE[8], IM[8];
    // R1: S=0
#pragma unroll
    for (int vp = 0; vp < 2; vp++) {
        u32 Tp = ((u32)vp << 8) | T;
        u32 tb = swz(Tp << 3) * 8u;
        lds8<0, IMOFF>(RE, IM, s, tb);
        gate8<0>(RE, IM, sg + 21 * 12);
        gate8<1>(RE, IM, sg + 20 * 12);
        gate8<2>(RE, IM, sg + 19 * 12);
        sts8<0, IMOFF>(RE, IM, s, tb);
    }
    __syncwarp();
    // R2: S=3 (warp-local exchange with R1)
#pragma unroll
    for (int vp = 0; vp < 2; vp++) {
        u32 Tp = ((u32)vp << 8) | T;
        u32 tb = swz(((Tp >> 3) << 6) | (Tp & 7u)) * 8u;
        lds8<3, IMOFF>(RE, IM, s, tb);
        gate8<0>(RE, IM, sg + 18 * 12);
        gate8<1>(RE, IM, sg + 17 * 12);
        gate8<2>(RE, IM, sg + 16 * 12);
        sts8<3, IMOFF>(RE, IM, s, tb);
    }
    __syncthreads();
    // R3: S=6 + fused coalesced store
#pragma unroll
    for (int vp = 0; vp < 2; vp++) {
        u32 Tp = ((u32)vp << 8) | T;
        u32 tp = ((Tp >> 6) << 9) | (Tp & 63u);
        u32 tb = swz(tp) * 8u;
        lds8<6, IMOFF>(RE, IM, s, tb);
        gate8<0>(RE, IM, sg + 15 * 12);
        gate8<1>(RE, IM, sg + 14 * 12);
        gate8<2>(RE, IM, sg + 13 * 12);
#pragma unroll
        for (int m = 0; m < 8; m++) {
            u32 amp = base | tp | ((u32)m << 6);
            float2 lo; lo.x = plo(RE[m]); lo.y = plo(IM[m]);
            float2 hi; hi.x = phi(RE[m]); hi.y = phi(IM[m]);
            g_buf0[amp] = lo;
            g_buf0[amp | 0x1000u] = hi;
        }
    }
}

__global__ void __launch_bounds__(256, 3) k_passA0(const float* __restrict__ re_in,
                                                   const float* __restrict__ im_in) {
    extern __shared__ char s[];   // 64KB
    __shared__ u64 s_gate[264];
    __shared__ float s_nrm[8];
    const int IMOFF = 32768;
    u32 T = threadIdx.x;
    u32 base = (u32)blockIdx.x << 13;
    for (u32 i = T; i < 264; i += 256) s_gate[i] = g_gpk[i];  // layer 0

    u64 nacc = 0;
#pragma unroll
    for (int vp = 0; vp < 2; vp++) {
        u32 Tp = ((u32)vp << 8) | T;
        u64 RE[8], IM[8];
#pragma unroll
        for (int m = 0; m < 8; m++) {
            u32 a0 = base | ((u32)m << 9) | Tp;
            u32 a1 = a0 | 0x1000u;
            RE[m] = pk2(re_in[a0], re_in[a1]);
            IM[m] = pk2(im_in[a0], im_in[a1]);
            nacc = pfma(RE[m], RE[m], nacc);
            nacc = pfma(IM[m], IM[m], nacc);
        }
        if (vp == 0) __syncthreads();   // staging visible before first gate use
        gate8<0>(RE, IM, s_gate + 12 * 12);
        gate8<1>(RE, IM, s_gate + 11 * 12);
        gate8<2>(RE, IM, s_gate + 10 * 12);
        sts8<9, IMOFF>(RE, IM, s, swz(Tp) * 8u);
    }
    {
        float nrm = plo(nacc) + phi(nacc);
#pragma unroll
        for (int o = 16; o > 0; o >>= 1) nrm += __shfl_down_sync(0xffffffffu, nrm, o);
        if ((T & 31) == 0) s_nrm[T >> 5] = nrm;
    }
    __syncthreads();
    if (T == 0) {
        float sum = 0.f;
#pragma unroll
        for (int w = 0; w < 8; w++) sum += s_nrm[w];
        atomicAdd(&g_norm, sum);
    }
    passA_R1to3(s, s_gate, T, base);
}

__global__ void __launch_bounds__(256, 3) k_passAg(int layer) {
    extern __shared__ char s[];
    __shared__ u64 s_gate[264];
    const int IMOFF = 32768;
    u32 T = threadIdx.x;
    u32 base = (u32)blockIdx.x << 13;
    for (u32 i = T; i < 264; i += 256) s_gate[i] = g_gpk[layer * 264 + i];

#pragma unroll
    for (int vp = 0; vp < 2; vp++) {
        u32 Tp = ((u32)vp << 8) | T;
        u64 RE[8], IM[8];
#pragma unroll
        for (int m = 0; m < 8; m++) {
            u32 g0 = base | ((u32)m << 9) | Tp;
            u32 a0 = g0 ^ (g0 >> 1);   // binary->Gray: fused inverse CNOT chain
            u32 a1 = a0 ^ 0x1800u;     // pack partner (glob bit 12 flipped pre-perm)
            float2 v0 = g_buf1[a0], v1 = g_buf1[a1];
            RE[m] = pk2(v0.x, v1.x);
            IM[m] = pk2(v0.y, v1.y);
        }
        if (vp == 0) __syncthreads();   // staging visible
        gate8<0>(RE, IM, s_gate + 12 * 12);
        gate8<1>(RE, IM, s_gate + 11 * 12);
        gate8<2>(RE, IM, s_gate + 10 * 12);
        sts8<9, IMOFF>(RE, IM, s, swz(Tp) * 8u);
    }
    __syncthreads();
    passA_R1to3(s, s_gate, T, base);
}

// ============ Pass B: gates glob 12..21 (wires 9..0). Tile = glob {0,1}+{12..21}
// (4096 amps, 32KB), pack on glob bit 0. Slot e (11 bits): e0=glob1, e[1..10]=glob[12..21].
// R0: gmem float4 load + window e[8..10] (wires 2,1,0)  [lanes in e0..7 -> 32B chunks]
// R1: S=0 (gates e1,e2 -> wires 9,8)   R2: S=3 (e3..5 -> 7,6,5)  [warp-local]
// R3: S=6 4-slot (e6,e7 -> 4,3) + gmem float4 store ============
__device__ __forceinline__ u32 gbOf(u32 e, u32 bb) {
    return ((e >> 1) << 12) | (bb << 2) | ((e & 1u) << 1);
}

template <int LAST>
__device__ __forceinline__ void passB_body(const u64* sg, char* s, u32 T, u32 bb,
                                           u64* RE, u64* IM) {
    const int IMOFF = 16384;
    // R0: direct load, window S=8
    {
#pragma unroll
        for (int m = 0; m < 8; m++) {
            u32 e = ((u32)m << 8) | T;
            float4 v = *(const float4*)&g_buf0[gbOf(e, bb)];
            RE[m] = pk2(v.x, v.z);
            IM[m] = pk2(v.y, v.w);
        }
        __syncthreads();   // staging visible
        gate8<0>(RE, IM, sg + 2 * 12);
        gate8<1>(RE, IM, sg + 1 * 12);
        gate8<2>(RE, IM, sg + 0 * 12);
        sts8<8, IMOFF>(RE, IM, s, swz(T) * 8u);
    }
    __syncthreads();
    // R1: S=0 (gates e1,e2)
    {
        u32 tb = swz(T << 3) * 8u;
        lds8<0, IMOFF>(RE, IM, s, tb);
        gate8<1>(RE, IM, sg + 9 * 12);
        gate8<2>(RE, IM, sg + 8 * 12);
        sts8<0, IMOFF>(RE, IM, s, tb);
    }
    __syncwarp();
    // R2: S=3 (warp-local with R1)
    {
        u32 tb = swz(((T >> 3) << 6) | (T & 7u)) * 8u;
        lds8<3, IMOFF>(RE, IM, s, tb);
        gate8<0>(RE, IM, sg + 7 * 12);
        gate8<1>(RE, IM, sg + 6 * 12);
        gate8<2>(RE, IM, sg + 5 * 12);
        sts8<3, IMOFF>(RE, IM, s, tb);
    }
    __syncthreads();
}

__global__ void __launch_bounds__(256, 3) k_passB(int layer) {
    __shared__ char s[32768];
    __shared__ u64 s_gate[264];
    const int IMOFF = 16384;
    u32 T = threadIdx.x, bb = blockIdx.x;
    for (u32 i = T; i < 264; i += 256) s_gate[i] = g_gpk[layer * 264 + i];
    u64 RE[8], IM[8];
    passB_body<0>(s_gate, s, T, bb, RE, IM);
    // R3: S=6 4-slot windows x2, gates e6,e7, fused store
#pragma unroll
    for (int v = 0; v < 2; v++) {
        u32 V = ((u32)v << 8) | T;
        u32 tp = ((V >> 6) << 8) | (V & 63u);
        u32 tb = swz(tp) * 8u;
        lds4<6, IMOFF>(RE, IM, s, tb);
        gate4<0>(RE, IM, s_gate + 4 * 12);
        gate4<1>(RE, IM, s_gate + 3 * 12);
#pragma unroll
        for (int m = 0; m < 4; m++) {
            u32 e = tp | ((u32)m << 6);
            float4 w; w.x = plo(RE[m]); w.y = plo(IM[m]); w.z = phi(RE[m]); w.w = phi(IM[m]);
            *(float4*)&g_buf1[gbOf(e, bb)] = w;
        }
    }
}

// Final pass B: fold the last CNOT permutation into indices and reduce <Z_q> directly.
__global__ void __launch_bounds__(256, 2) k_passB_last() {
    __shared__ char s[32768];
    __shared__ u64 s_gate[264];
    __shared__ float s_part[NQ * 8];
    const int IMOFF = 16384;
    u32 T = threadIdx.x, bb = blockIdx.x;
    for (u32 i = T; i < 264; i += 256) s_gate[i] = g_gpk[3 * 264 + i];
    u64 RE[8], IM[8];
    passB_body<1>(s_gate, s, T, bb, RE, IM);

    float acc[NQ];
#pragma unroll
    for (int q = 0; q < NQ; q++) acc[q] = 0.f;
#pragma unroll
    for (int v = 0; v < 2; v++) {
        u32 V = ((u32)v << 8) | T;
        u32 tp = ((V >> 6) << 8) | (V & 63u);
        u32 tb = swz(tp) * 8u;
        lds4<6, IMOFF>(RE, IM, s, tb);
        gate4<0>(RE, IM, s_gate + 4 * 12);
        gate4<1>(RE, IM, s_gate + 3 * 12);
#pragma unroll
        for (int m = 0; m < 4; m++) {
            u32 e = tp | ((u32)m << 6);
            u32 glob = gbOf(e, bb);   // k=0 amp (glob bit0 = 0)
            u64 P = pfma(RE[m], RE[m], pmul(IM[m], IM[m]));
            float p0 = plo(P), p1 = phi(P);
            float sv = p0 + p1, dv = p0 - p1;
            u32 x = glob;   // forward CNOT-chain permutation (suffix xor)
            x ^= x >> 1; x ^= x >> 2; x ^= x >> 4; x ^= x >> 8; x ^= x >> 16;
#pragma unroll
            for (int q = 0; q < 21; q++)
                acc[q] += ((x >> (21 - q)) & 1u) ? -sv : sv;
            acc[21] += (x & 1u) ? -dv : dv;   // packed partner flips x bit0 only (wire 21)
        }
    }
#pragma unroll
    for (int q = 0; q < NQ; q++) {
        float v2 = acc[q];
#pragma unroll
        for (int o = 16; o > 0; o >>= 1) v2 += __shfl_down_sync(0xffffffffu, v2, o);
        if ((T & 31) == 0) s_part[q * 8 + (T >> 5)] = v2;
    }
    __syncthreads();
    if (T < NQ) {
        float sum = 0.f;
#pragma unroll
        for (int w = 0; w < 8; w++) sum += s_part[T * 8 + w];
        atomicAdd(&g_acc[T], sum);
    }
}

extern "C" void kernel_launch(void* const* d_in, const int* in_sizes, int n_in,
                              void* d_out, int out_size) {
    const float* params = (const float*)d_in[0];
    const float* sre = (const float*)d_in[1];
    const float* sim = (const float*)d_in[2];
    float* out = (float*)d_out;

    cudaFuncSetAttribute(k_passA0, cudaFuncAttributeMaxDynamicSharedMemorySize, 65536);
    cudaFuncSetAttribute(k_passAg, cudaFuncAttributeMaxDynamicSharedMemorySize, 65536);

    k_gates<<<1, 128>>>(params);
    k_passA0<<<512, 256, 65536>>>(sre, sim);
    k_passB<<<1024, 256>>>(0);
    for (int l = 1; l < 4; l++) {
        k_passAg<<<512, 256, 65536>>>(l);
        if (l < 3) k_passB<<<1024, 256>>>(l);
        else       k_passB_last<<<1024, 256>>>();
    }
    k_final<<<1, 32>>>(out);
}

// round 16
// speedup vs baseline: 1.1045x; 1.0023x over previous
#include <cuda_runtime.h>

typedef unsigned long long u64;
typedef unsigned int u32;

#define NQ 22
#define DIM (1u << 22)

__device__ float2 g_buf0[DIM];
__device__ float2 g_buf1[DIM];
// per (layer,qubit): {u00r,u00i,-u00i, u01r,u01i,-u01i, u10r,u10i,-u10i, u11r,u11i,-u11i}
__device__ u64 g_gpk[4 * 22 * 12];
__device__ float g_norm;
__device__ float g_acc[NQ];

// ---------- packed f32x2 helpers ----------
__device__ __forceinline__ u64 pmul(u64 a, u64 b) {
    u64 d; asm("mul.rn.f32x2 %0, %1, %2;" : "=l"(d) : "l"(a), "l"(b)); return d;
}
__device__ __forceinline__ u64 pfma(u64 a, u64 b, u64 c) {
    u64 d; asm("fma.rn.f32x2 %0, %1, %2, %3;" : "=l"(d) : "l"(a), "l"(b), "l"(c)); return d;
}
__device__ __forceinline__ u64 pk2(float lo, float hi) {
    return ((u64)__float_as_uint(hi) << 32) | (u64)__float_as_uint(lo);
}
__device__ __forceinline__ float plo(u64 v) { return __uint_as_float((u32)v); }
__device__ __forceinline__ float phi(u64 v) { return __uint_as_float((u32)(v >> 32)); }

// XOR-linear swizzle on 8B slot index; bank-pair map verified invertible for all windows
__host__ __device__ constexpr u32 swz(u32 j) { return j ^ ((j >> 3) & 15u) ^ ((j >> 7) & 15u); }

// ---------- gate precompute ----------
__global__ void k_gates(const float* __restrict__ P) {
    int t = threadIdx.x;
    if (t < NQ) g_acc[t] = 0.f;
    if (t == NQ) g_norm = 0.f;
    if (t >= 88) return;  // t = l*22 + q
    float tx = P[t * 3 + 0], ty = P[t * 3 + 1], tz = P[t * 3 + 2];
    float cx = cosf(0.5f * tx), sx = sinf(0.5f * tx);
    float cy = cosf(0.5f * ty), sy = sinf(0.5f * ty);
    float cz = cosf(0.5f * tz), sz = sinf(0.5f * tz);
    float m00r = cy * cx, m00i = sy * sx;
    float m01r = -sy * cx, m01i = -cy * sx;
    float m10r = sy * cx, m10i = -cy * sx;
    float m11r = cy * cx, m11i = -sy * sx;
    float u00r = cz * m00r + sz * m00i, u00i = cz * m00i - sz * m00r;
    float u01r = cz * m01r + sz * m01i, u01i = cz * m01i - sz * m01r;
    float u10r = cz * m10r - sz * m10i, u10i = cz * m10i + sz * m10r;
    float u11r = cz * m11r - sz * m11i, u11i = cz * m11i + sz * m11r;
    float vals[12] = { u00r, u00i, -u00i, u01r, u01i, -u01i,
                       u10r, u10i, -u10i, u11r, u11i, -u11i };
    u64* W = g_gpk + t * 12;
#pragma unroll
    for (int i = 0; i < 12; i++) {
        u32 b = __float_as_uint(vals[i]);
        W[i] = ((u64)b << 32) | (u64)b;
    }
}

__global__ void k_final(float* __restrict__ out) {
    if (threadIdx.x < NQ) out[threadIdx.x] = g_acc[threadIdx.x] / g_norm;
}

// ---------- register gate on bit G of an 8-slot window ----------
template <int G>
__device__ __forceinline__ void gate8(u64* RE, u64* IM, const u64* W) {
    u64 p00r = W[0], p00i = W[1], n00i = W[2], p01r = W[3], p01i = W[4], n01i = W[5];
    u64 p10r = W[6], p10i = W[7], n10i = W[8], p11r = W[9], p11i = W[10], n11i = W[11];
#pragma unroll
    for (int h = 0; h < 4; h++) {
        const int m0 = ((h >> G) << (G + 1)) | (h & ((1 << G) - 1));
        const int m1 = m0 | (1 << G);
        u64 ar = RE[m0], ai = IM[m0], br = RE[m1], bi = IM[m1];
        u64 t0 = pmul(p00r, ar); t0 = pfma(n00i, ai, t0); t0 = pfma(p01r, br, t0); t0 = pfma(n01i, bi, t0);
        u64 t1 = pmul(p00i, ar); t1 = pfma(p00r, ai, t1); t1 = pfma(p01i, br, t1); t1 = pfma(p01r, bi, t1);
        u64 t2 = pmul(p10r, ar); t2 = pfma(n10i, ai, t2); t2 = pfma(p11r, br, t2); t2 = pfma(n11i, bi, t2);
        u64 t3 = pmul(p10i, ar); t3 = pfma(p10r, ai, t3); t3 = pfma(p11i, br, t3); t3 = pfma(p11r, bi, t3);
        RE[m0] = t0; IM[m0] = t1; RE[m1] = t2; IM[m1] = t3;
    }
}
template <int G>
__device__ __forceinline__ void gate4(u64* RE, u64* IM, const u64* W) {
    u64 p00r = W[0], p00i = W[1], n00i = W[2], p01r = W[3], p01i = W[4], n01i = W[5];
    u64 p10r = W[6], p10i = W[7], n10i = W[8], p11r = W[9], p11i = W[10], n11i = W[11];
#pragma unroll
    for (int h = 0; h < 2; h++) {
        const int m0 = ((h >> G) << (G + 1)) | (h & ((1 << G) - 1));
        const int m1 = m0 | (1 << G);
        u64 ar = RE[m0], ai = IM[m0], br = RE[m1], bi = IM[m1];
        u64 t0 = pmul(p00r, ar); t0 = pfma(n00i, ai, t0); t0 = pfma(p01r, br, t0); t0 = pfma(n01i, bi, t0);
        u64 t1 = pmul(p00i, ar); t1 = pfma(p00r, ai, t1); t1 = pfma(p01i, br, t1); t1 = pfma(p01r, bi, t1);
        u64 t2 = pmul(p10r, ar); t2 = pfma(n10i, ai, t2); t2 = pfma(p11r, br, t2); t2 = pfma(n11i, bi, t2);
        u64 t3 = pmul(p10i, ar); t3 = pfma(p10r, ai, t3); t3 = pfma(p11i, br, t3); t3 = pfma(p11r, bi, t3);
        RE[m0] = t0; IM[m0] = t1; RE[m1] = t2; IM[m1] = t3;
    }
}

// ---------- smem window ops: slot j at byte swz(j)*8; IM at +IMOFF ----------
template <int S, int IMOFF>
__device__ __forceinline__ void lds8(u64* RE, u64* IM, const char* s, u32 tb8) {
#pragma unroll
    for (int m = 0; m < 8; m++) {
        u32 a = tb8 ^ (swz((u32)m << S) * 8u);
        RE[m] = *(const u64*)(s + a);
        IM[m] = *(const u64*)(s + a + IMOFF);
    }
}
template <int S, int IMOFF>
__device__ __forceinline__ void sts8(const u64* RE, const u64* IM, char* s, u32 tb8) {
#pragma unroll
    for (int m = 0; m < 8; m++) {
        u32 a = tb8 ^ (swz((u32)m << S) * 8u);
        *(u64*)(s + a) = RE[m];
        *(u64*)(s + a + IMOFF) = IM[m];
    }
}
template <int S, int IMOFF>
__device__ __forceinline__ void lds4(u64* RE, u64* IM, const char* s, u32 tb8) {
#pragma unroll
    for (int m = 0; m < 4; m++) {
        u32 a = tb8 ^ (swz((u32)m << S) * 8u);
        RE[m] = *(const u64*)(s + a);
        IM[m] = *(const u64*)(s + a + IMOFF);
    }
}

// ============ Pass A (R7 shape, measured 23.8us): gates glob 0..10 (wires 21..11).
// Tile 4096 amps (glob 0..11), pack on glob bit 11. Slot j (11 bits) = glob 0..10.
// R0 bits 3-5 (gmem load), R1 bits 0-2, R2 bits 6-8, R3 bits 9-10 (gmem store). ============
__device__ __forceinline__ void passA_tail(char* s, const u64* sg, u32 T, u32 base) {
    const int IMOFF = 16384;
    u64 RE[8], IM[8];
    // R1: S=0, slot bits 0,1,2 -> wires 21,20,19
    u32 tb = swz(T << 3) * 8u;
    lds8<0, IMOFF>(RE, IM, s, tb);
    gate8<0>(RE, IM, sg + 21 * 12);
    gate8<1>(RE, IM, sg + 20 * 12);
    gate8<2>(RE, IM, sg + 19 * 12);
    sts8<0, IMOFF>(RE, IM, s, tb);
    __syncthreads();
    // R2: S=6, bits 6,7,8 -> wires 15,14,13
    tb = swz(((T >> 6) << 9) | (T & 63u)) * 8u;
    lds8<6, IMOFF>(RE, IM, s, tb);
    gate8<0>(RE, IM, sg + 15 * 12);
    gate8<1>(RE, IM, sg + 14 * 12);
    gate8<2>(RE, IM, sg + 13 * 12);
    sts8<6, IMOFF>(RE, IM, s, tb);
    __syncthreads();
    // R3: bits 9,10 -> wires 12,11 (4-slot windows x2), fused coalesced store
#pragma unroll
    for (int v = 0; v < 2; v++) {
        u32 V = ((u32)v << 8) | T;
        u32 tb4 = swz(V) * 8u;
        lds4<9, IMOFF>(RE, IM, s, tb4);
        gate4<0>(RE, IM, sg + 12 * 12);
        gate4<1>(RE, IM, sg + 11 * 12);
#pragma unroll
        for (int m = 0; m < 4; m++) {
            u32 amp = base | ((u32)m << 9) | V;
            float2 lo; lo.x = plo(RE[m]); lo.y = plo(IM[m]);
            float2 hi; hi.x = phi(RE[m]); hi.y = phi(IM[m]);
            g_buf0[amp] = lo;
            g_buf0[amp | 0x800u] = hi;
        }
    }
}

__global__ void __launch_bounds__(256, 3) k_passA0(const float* __restrict__ re_in,
                                                   const float* __restrict__ im_in) {
    __shared__ char s[32768];
    __shared__ u64 s_gate[264];
    __shared__ float s_nrm[8];
    const int IMOFF = 16384;
    u32 T = threadIdx.x;
    u32 base = (u32)blockIdx.x << 12;
    for (u32 i = T; i < 264; i += 256) s_gate[i] = g_gpk[i];  // layer 0

    u64 RE[8], IM[8];
    u64 nacc = 0;
    u32 tbase = ((T >> 3) << 6) | (T & 7u);
#pragma unroll
    for (int m = 0; m < 8; m++) {
        u32 j = tbase | ((u32)m << 3);
        u32 a0 = base | j, a1 = a0 | 0x800u;
        RE[m] = pk2(re_in[a0], re_in[a1]);
        IM[m] = pk2(im_in[a0], im_in[a1]);
        nacc = pfma(RE[m], RE[m], nacc);
        nacc = pfma(IM[m], IM[m], nacc);
    }
    float nrm = plo(nacc) + phi(nacc);
#pragma unroll
    for (int o = 16; o > 0; o >>= 1) nrm += __shfl_down_sync(0xffffffffu, nrm, o);
    if ((T & 31) == 0) s_nrm[T >> 5] = nrm;
    __syncthreads();  // staging + s_nrm visible
    if (T == 0) {
        float sum = 0.f;
#pragma unroll
        for (int w = 0; w < 8; w++) sum += s_nrm[w];
        atomicAdd(&g_norm, sum);
    }
    // R0: window bits 3,4,5 -> wires 18,17,16
    gate8<0>(RE, IM, s_gate + 18 * 12);
    gate8<1>(RE, IM, s_gate + 17 * 12);
    gate8<2>(RE, IM, s_gate + 16 * 12);
    sts8<3, IMOFF>(RE, IM, s, swz(tbase) * 8u);
    __syncthreads();
    passA_tail(s, s_gate, T, base);
}

__global__ void __launch_bounds__(256, 3) k_passAg(int layer) {
    __shared__ char s[32768];
    __shared__ u64 s_gate[264];
    const int IMOFF = 16384;
    u32 T = threadIdx.x;
    u32 base = (u32)blockIdx.x << 12;
    for (u32 i = T; i < 264; i += 256) s_gate[i] = g_gpk[layer * 264 + i];

    u64 RE[8], IM[8];
    u32 tbase = ((T >> 3) << 6) | (T & 7u);
#pragma unroll
    for (int m = 0; m < 8; m++) {
        u32 g0 = base | tbase | ((u32)m << 3);
        u32 a0 = g0 ^ (g0 >> 1);   // binary->Gray: fused inverse CNOT chain
        u32 a1 = a0 ^ 0xC00u;      // pack partner (glob bit 11 flipped pre-perm)
        float2 v0 = g_buf1[a0], v1 = g_buf1[a1];
        RE[m] = pk2(v0.x, v1.x);
        IM[m] = pk2(v0.y, v1.y);
    }
    __syncthreads();  // staging visible
    gate8<0>(RE, IM, s_gate + 18 * 12);
    gate8<1>(RE, IM, s_gate + 17 * 12);
    gate8<2>(RE, IM, s_gate + 16 * 12);
    sts8<3, IMOFF>(RE, IM, s, swz(tbase) * 8u);
    __syncthreads();
    passA_tail(s, s_gate, T, base);
}

// ============ Pass B: gates glob 11..21 (wires 10..0). Tile = glob {0,1}+{11..21}
// (8192 amps, 64KB), pack on glob bit 0. Slot e (12 bits): e0=glob1, e[1..11]=glob[11..21].
// Gmem-facing windows keep register bits HIGH (e9..11 / e6..8) so lanes form 32B chunks.
// R0: float4 load + gates e9..11 (wires 2,1,0)   R1: S=0 gates e1,e2 (wires 10,9)
// R2: S=3 gates e3..5 (wires 8,7,6) [warp-local with R1]
// R3: S=6 gates e6..8 (wires 5,4,3) + fused float4 store ============
__device__ __forceinline__ u32 gbOf(u32 e, u32 bb) {
    return ((e >> 1) << 11) | (bb << 2) | ((e & 1u) << 1);
}

template <int LAST>
__device__ __forceinline__ void passB_R0to2(const u64* sg, char* s, u32 T, u32 bb) {
    const int IMOFF = 32768;
    // R0: direct load (lanes -> e0..4 -> 32B chunks), window S=9
#pragma unroll
    for (int vp = 0; vp < 2; vp++) {
        u32 Tp = ((u32)vp << 8) | T;
        u64 RE[8], IM[8];
#pragma unroll
        for (int m = 0; m < 8; m++) {
            u32 e = ((u32)m << 9) | Tp;
            float4 v = *(const float4*)&g_buf0[gbOf(e, bb)];
            RE[m] = pk2(v.x, v.z);
            IM[m] = pk2(v.y, v.w);
        }
        if (vp == 0) __syncthreads();   // gate table visible
        gate8<0>(RE, IM, sg + 2 * 12);
        gate8<1>(RE, IM, sg + 1 * 12);
        gate8<2>(RE, IM, sg + 0 * 12);
        sts8<9, IMOFF>(RE, IM, s, swz(Tp) * 8u);
    }
    __syncthreads();
    // R1: S=0, gates e1,e2 -> wires 10,9
#pragma unroll
    for (int vp = 0; vp < 2; vp++) {
        u32 Tp = ((u32)vp << 8) | T;
        u64 RE[8], IM[8];
        u32 tb = swz(Tp << 3) * 8u;
        lds8<0, IMOFF>(RE, IM, s, tb);
        gate8<1>(RE, IM, sg + 10 * 12);
        gate8<2>(RE, IM, sg + 9 * 12);
        sts8<0, IMOFF>(RE, IM, s, tb);
    }
    __syncwarp();
    // R2: S=3, gates e3..5 -> wires 8,7,6 (warp-local exchange with R1)
#pragma unroll
    for (int vp = 0; vp < 2; vp++) {
        u32 Tp = ((u32)vp << 8) | T;
        u64 RE[8], IM[8];
        u32 tb = swz(((Tp >> 3) << 6) | (Tp & 7u)) * 8u;
        lds8<3, IMOFF>(RE, IM, s, tb);
        gate8<0>(RE, IM, sg + 8 * 12);
        gate8<1>(RE, IM, sg + 7 * 12);
        gate8<2>(RE, IM, sg + 6 * 12);
        sts8<3, IMOFF>(RE, IM, s, tb);
    }
    __syncthreads();
}

__global__ void __launch_bounds__(256, 3) k_passB(int layer) {
    extern __shared__ char s[];   // 64KB
    __shared__ u64 s_gate[264];
    const int IMOFF = 32768;
    u32 T = threadIdx.x, bb = blockIdx.x;
    for (u32 i = T; i < 264; i += 256) s_gate[i] = g_gpk[layer * 264 + i];
    passB_R0to2<0>(s_gate, s, T, bb);
    // R3: S=6, gates e6..8 -> wires 5,4,3; fused float4 store (lanes -> e0..5)
#pragma unroll
    for (int vp = 0; vp < 2; vp++) {
        u32 Tp = ((u32)vp << 8) | T;
        u64 RE[8], IM[8];
        u32 tp = ((Tp >> 6) << 9) | (Tp & 63u);
        u32 tb = swz(tp) * 8u;
        lds8<6, IMOFF>(RE, IM, s, tb);
        gate8<0>(RE, IM, s_gate + 5 * 12);
        gate8<1>(RE, IM, s_gate + 4 * 12);
        gate8<2>(RE, IM, s_gate + 3 * 12);
#pragma unroll
        for (int m = 0; m < 8; m++) {
            u32 e = tp | ((u32)m << 6);
            float4 w; w.x = plo(RE[m]); w.y = plo(IM[m]); w.z = phi(RE[m]); w.w = phi(IM[m]);
            *(float4*)&g_buf1[gbOf(e, bb)] = w;
        }
    }
}

// Final pass B: fold the last CNOT permutation into indices and reduce <Z_q> directly.
__global__ void __launch_bounds__(256, 2) k_passB_last() {
    extern __shared__ char s[];
    __shared__ u64 s_gate[264];
    __shared__ float s_part[NQ * 8];
    const int IMOFF = 32768;
    u32 T = threadIdx.x, bb = blockIdx.x;
    for (u32 i = T; i < 264; i += 256) s_gate[i] = g_gpk[3 * 264 + i];
    passB_R0to2<1>(s_gate, s, T, bb);

    float acc[NQ];
#pragma unroll
    for (int q = 0; q < NQ; q++) acc[q] = 0.f;
#pragma unroll
    for (int vp = 0; vp < 2; vp++) {
        u32 Tp = ((u32)vp << 8) | T;
        u64 RE[8], IM[8];
        u32 tp = ((Tp >> 6) << 9) | (Tp & 63u);
        u32 tb = swz(tp) * 8u;
        lds8<6, IMOFF>(RE, IM, s, tb);
        gate8<0>(RE, IM, s_gate + 5 * 12);
        gate8<1>(RE, IM, s_gate + 4 * 12);
        gate8<2>(RE, IM, s_gate + 3 * 12);
#pragma unroll
        for (int m = 0; m < 8; m++) {
            u32 e = tp | ((u32)m << 6);
            u32 glob = gbOf(e, bb);   // k=0 amp (glob bit0 = 0)
            u64 P = pfma(RE[m], RE[m], pmul(IM[m], IM[m]));
            float p0 = plo(P), p1 = phi(P);
            float sv = p0 + p1, dv = p0 - p1;
            u32 x = glob;   // forward CNOT-chain permutation (suffix xor)
            x ^= x >> 1; x ^= x >> 2; x ^= x >> 4; x ^= x >> 8; x ^= x >> 16;
#pragma unroll
            for (int q = 0; q < 21; q++)
                acc[q] += ((x >> (21 - q)) & 1u) ? -sv : sv;
            acc[21] += (x & 1u) ? -dv : dv;   // packed partner flips x bit0 only (wire 21)
        }
    }
#pragma unroll
    for (int q = 0; q < NQ; q++) {
        float v2 = acc[q];
#pragma unroll
        for (int o = 16; o > 0; o >>= 1) v2 += __shfl_down_sync(0xffffffffu, v2, o);
        if ((T & 31) == 0) s_part[q * 8 + (T >> 5)] = v2;
    }
    __syncthreads();
    if (T < NQ) {
        float sum = 0.f;
#pragma unroll
        for (int w = 0; w < 8; w++) sum += s_part[T * 8 + w];
        atomicAdd(&g_acc[T], sum);
    }
}

extern "C" void kernel_launch(void* const* d_in, const int* in_sizes, int n_in,
                              void* d_out, int out_size) {
    const float* params = (const float*)d_in[0];
    const float* sre = (const float*)d_in[1];
    const float* sim = (const float*)d_in[2];
    float* out = (float*)d_out;

    cudaFuncSetAttribute(k_passB, cudaFuncAttributeMaxDynamicSharedMemorySize, 65536);
    cudaFuncSetAttribute(k_passB_last, cudaFuncAttributeMaxDynamicSharedMemorySize, 65536);

    k_gates<<<1, 128>>>(params);
    k_passA0<<<1024, 256>>>(sre, sim);
    k_passB<<<512, 256, 65536>>>(0);
    for (int l = 1; l < 4; l++) {
        k_passAg<<<1024, 256>>>(l);
        if (l < 3) k_passB<<<512, 256, 65536>>>(l);
        else       k_passB_last<<<512, 256, 65536>>>();
    }
    k_final<<<1, 32>>>(out);
}